// round 14
// baseline (speedup 1.0000x reference)
#include <cuda_runtime.h>
#include <cuda_bf16.h>
#include <cstdint>

#define BATCH 2
#define SEQ   2048
#define DMODEL 1024
#define NHEAD 16
#define HDIM  64
#define HWIN  64
#define MROWS (BATCH*SEQ)

// ---------------- scratch ----------------
__device__ float g_q[(size_t)MROWS * DMODEL];
__device__ float g_k[(size_t)MROWS * DMODEL];
__device__ float g_v[(size_t)MROWS * DMODEL];
__device__ float g_ctx[(size_t)MROWS * DMODEL];
__device__ __nv_bfloat16 g_xh[(size_t)MROWS * DMODEL];
__device__ __nv_bfloat16 g_xl[(size_t)MROWS * DMODEL];
__device__ __nv_bfloat16 g_ch[(size_t)MROWS * DMODEL];
__device__ __nv_bfloat16 g_cl[(size_t)MROWS * DMODEL];
__device__ __nv_bfloat16 g_wh[4][(size_t)DMODEL * DMODEL];
__device__ __nv_bfloat16 g_wl[4][(size_t)DMODEL * DMODEL];

// ---------------- helpers ----------------
__device__ __forceinline__ uint32_t smem_u32(const void* p) {
    uint32_t a;
    asm("{ .reg .u64 t; cvta.to.shared.u64 t, %1; cvt.u32.u64 %0, t; }" : "=r"(a) : "l"(p));
    return a;
}
__device__ __forceinline__ void cp16(uint32_t s, const void* g) {
    asm volatile("cp.async.cg.shared.global [%0], [%1], 16;" :: "r"(s), "l"(g));
}
#define CP_COMMIT() asm volatile("cp.async.commit_group;" ::: "memory")
#define CP_WAIT0()  asm volatile("cp.async.wait_group 0;" ::: "memory")

#define LDSM_X4(r0,r1,r2,r3,addr) \
    asm volatile("ldmatrix.sync.aligned.m8n8.x4.shared.b16 {%0,%1,%2,%3}, [%4];" \
                 : "=r"(r0), "=r"(r1), "=r"(r2), "=r"(r3) : "r"(addr))

#define MMA16816(d, a0,a1,a2,a3, b0,b1) \
    asm volatile("mma.sync.aligned.m16n8k16.row.col.f32.bf16.bf16.f32 " \
                 "{%0,%1,%2,%3}, {%4,%5,%6,%7}, {%8,%9}, {%0,%1,%2,%3};" \
                 : "+f"((d)[0]), "+f"((d)[1]), "+f"((d)[2]), "+f"((d)[3]) \
                 : "r"(a0), "r"(a1), "r"(a2), "r"(a3), "r"(b0), "r"(b1))

// ---------------- split fp32 -> bf16 hi + bf16 residual --------------------
__device__ __forceinline__ void split1(float4 v, uint2& hp, uint2& lp) {
    __nv_bfloat16 hx = __float2bfloat16(v.x), hy = __float2bfloat16(v.y);
    __nv_bfloat16 hz = __float2bfloat16(v.z), hw = __float2bfloat16(v.w);
    float lx = v.x - __bfloat162float(hx), ly = v.y - __bfloat162float(hy);
    float lz = v.z - __bfloat162float(hz), lw = v.w - __bfloat162float(hw);
    hp.x = ((uint32_t)__bfloat16_as_ushort(hy) << 16) | __bfloat16_as_ushort(hx);
    hp.y = ((uint32_t)__bfloat16_as_ushort(hw) << 16) | __bfloat16_as_ushort(hz);
    lp.x = ((uint32_t)__bfloat16_as_ushort(__float2bfloat16(ly)) << 16) |
           __bfloat16_as_ushort(__float2bfloat16(lx));
    lp.y = ((uint32_t)__bfloat16_as_ushort(__float2bfloat16(lw)) << 16) |
           __bfloat16_as_ushort(__float2bfloat16(lz));
}

__global__ __launch_bounds__(256) void split_bf16(
    const float* __restrict__ src, __nv_bfloat16* __restrict__ hi,
    __nv_bfloat16* __restrict__ lo, int n4)
{
    int idx = blockIdx.x * 256 + threadIdx.x;
    int stride = gridDim.x * 256;
    for (; idx < n4; idx += stride) {
        uint2 hp, lp;
        split1(((const float4*)src)[idx], hp, lp);
        ((uint2*)hi)[idx] = hp;
        ((uint2*)lo)[idx] = lp;
    }
}

__global__ __launch_bounds__(256) void split_bf16x4(
    const float* __restrict__ s0, const float* __restrict__ s1,
    const float* __restrict__ s2, const float* __restrict__ s3,
    __nv_bfloat16* __restrict__ hi, __nv_bfloat16* __restrict__ lo, int per4)
{
    int idx = blockIdx.x * 256 + threadIdx.x;
    int stride = gridDim.x * 256;
    int n4 = 4 * per4;
    for (; idx < n4; idx += stride) {
        int m = idx / per4, loc = idx - m * per4;
        const float* s = (m == 0) ? s0 : (m == 1) ? s1 : (m == 2) ? s2 : s3;
        uint2 hp, lp;
        split1(((const float4*)s)[loc], hp, lp);
        ((uint2*)hi)[idx] = hp;
        ((uint2*)lo)[idx] = lp;
    }
}

// -------- tensor GEMM: fat chunks (Ah/Al/Bh/Bl co-resident), frag reuse ----
#define ROWB   80
#define TILEB  (128 * ROWB)
#define STAGE  (4 * TILEB)
#define NSTG   2
#define GEMM_SMEM (NSTG * STAGE)
#define NCHUNK 32

__global__ __launch_bounds__(512, 2) void gemm_tc(
    const __nv_bfloat16* __restrict__ Ah, const __nv_bfloat16* __restrict__ Al,
    const __nv_bfloat16* __restrict__ Whbase, const __nv_bfloat16* __restrict__ Wlbase,
    const float* __restrict__ bias0, const float* __restrict__ bias1,
    const float* __restrict__ bias2,
    float* __restrict__ C0, float* __restrict__ C1, float* __restrict__ C2)
{
    extern __shared__ char smem[];
    const uint32_t tiles = smem_u32(smem);

    const int z = blockIdx.z;
    const size_t WSZ = (size_t)DMODEL * DMODEL;
    const __nv_bfloat16* Bh = Whbase + (size_t)z * WSZ;
    const __nv_bfloat16* Bl = Wlbase + (size_t)z * WSZ;
    const float* bias = (z == 0) ? bias0 : (z == 1) ? bias1 : bias2;
    float* C = (z == 0) ? C0 : (z == 1) ? C1 : C2;

    const int tid = threadIdx.x;
    const int wid = tid >> 5, lane = tid & 31;
    const int wm = wid >> 2;
    const int wn = wid & 3;
    const int bm = blockIdx.y * 128;
    const int bn = blockIdx.x * 128;

    const int lr = tid >> 2;
    const int q16 = (tid & 3) * 16;

    float acc[2][4][4];
#pragma unroll
    for (int i = 0; i < 2; i++)
#pragma unroll
        for (int j = 0; j < 4; j++)
#pragma unroll
            for (int k = 0; k < 4; k++) acc[i][j][k] = 0.f;

    auto issue_load = [&](int c) {
        const int kk = c * 32;
        const size_t arow = (size_t)(bm + lr) * DMODEL + kk + q16 / 2;
        const size_t brow = (size_t)(bn + lr) * DMODEL + kk + q16 / 2;
        const uint32_t st = tiles + (c & 1) * STAGE;
        const uint32_t so = lr * ROWB + q16;
        cp16(st + so, Ah + arow);
        cp16(st + TILEB + so, Al + arow);
        cp16(st + 2 * TILEB + so, Bh + brow);
        cp16(st + 3 * TILEB + so, Bl + brow);
    };

    issue_load(0); CP_COMMIT();

    const uint32_t a_lrow = (uint32_t)(lane & 15) * ROWB + (uint32_t)(lane >> 4) * 16;
    const uint32_t b_lrow = (uint32_t)((lane >> 4) * 8 + (lane & 7)) * ROWB +
                            (uint32_t)((lane >> 3) & 1) * 16;

    for (int c = 0; c < NCHUNK; c++) {
        CP_WAIT0();
        __syncthreads();
        if (c + 1 < NCHUNK) issue_load(c + 1);
        CP_COMMIT();

        const uint32_t st = tiles + (c & 1) * STAGE;
        const uint32_t ahb = st + (uint32_t)(wm * 32) * ROWB + a_lrow;
        const uint32_t bhb = st + 2 * TILEB + (uint32_t)(wn * 32) * ROWB + b_lrow;

#pragma unroll
        for (int ks = 0; ks < 2; ks++) {
            const uint32_t koff = ks * 32;
            uint32_t ah[2][4], bh_[2][4], tf[2][4];
#pragma unroll
            for (int mt = 0; mt < 2; mt++)
                LDSM_X4(ah[mt][0], ah[mt][1], ah[mt][2], ah[mt][3],
                        ahb + (uint32_t)(mt * 16) * ROWB + koff);
#pragma unroll
            for (int np = 0; np < 2; np++)
                LDSM_X4(bh_[np][0], bh_[np][1], bh_[np][2], bh_[np][3],
                        bhb + (uint32_t)(np * 16) * ROWB + koff);
#pragma unroll
            for (int mt = 0; mt < 2; mt++)
#pragma unroll
                for (int nt = 0; nt < 4; nt++)
                    MMA16816(acc[mt][nt], ah[mt][0], ah[mt][1], ah[mt][2], ah[mt][3],
                             bh_[nt >> 1][(nt & 1) * 2], bh_[nt >> 1][(nt & 1) * 2 + 1]);
#pragma unroll
            for (int mt = 0; mt < 2; mt++)
                LDSM_X4(tf[mt][0], tf[mt][1], tf[mt][2], tf[mt][3],
                        ahb + TILEB + (uint32_t)(mt * 16) * ROWB + koff);
#pragma unroll
            for (int mt = 0; mt < 2; mt++)
#pragma unroll
                for (int nt = 0; nt < 4; nt++)
                    MMA16816(acc[mt][nt], tf[mt][0], tf[mt][1], tf[mt][2], tf[mt][3],
                             bh_[nt >> 1][(nt & 1) * 2], bh_[nt >> 1][(nt & 1) * 2 + 1]);
#pragma unroll
            for (int np = 0; np < 2; np++)
                LDSM_X4(tf[np][0], tf[np][1], tf[np][2], tf[np][3],
                        bhb + TILEB + (uint32_t)(np * 16) * ROWB + koff);
#pragma unroll
            for (int mt = 0; mt < 2; mt++)
#pragma unroll
                for (int nt = 0; nt < 4; nt++)
                    MMA16816(acc[mt][nt], ah[mt][0], ah[mt][1], ah[mt][2], ah[mt][3],
                             tf[nt >> 1][(nt & 1) * 2], tf[nt >> 1][(nt & 1) * 2 + 1]);
        }
    }

#pragma unroll
    for (int mt = 0; mt < 2; mt++) {
#pragma unroll
        for (int nt = 0; nt < 4; nt++) {
            const int r0 = bm + wm * 32 + mt * 16 + (lane >> 2);
            const int cc = bn + wn * 32 + nt * 8 + (lane & 3) * 2;
            const float b0 = bias[cc], b1 = bias[cc + 1];
            float2 v0, v1;
            v0.x = acc[mt][nt][0] + b0; v0.y = acc[mt][nt][1] + b1;
            v1.x = acc[mt][nt][2] + b0; v1.y = acc[mt][nt][3] + b1;
            *(float2*)&C[(size_t)r0 * DMODEL + cc] = v0;
            *(float2*)&C[(size_t)(r0 + 8) * DMODEL + cc] = v1;
        }
    }
}

// ---------------- banded attention: full-row single-pass writes ------------
#define QB 16
#define KSPAN 144
#define TPAD 17
#define PWW 160     // prob window width: 5 x 32 so the warp zero-loop covers ALL of it

__global__ __launch_bounds__(512) void local_attn_kernel(
    const float* __restrict__ Qg, const float* __restrict__ Kg,
    const float* __restrict__ Vg, float* __restrict__ attn,
    float* __restrict__ ctx)
{
    __shared__ float4 tile4[KSPAN][TPAD];
    __shared__ float4 qs4[QB][TPAD];
    __shared__ float ps[QB][KSPAN];
    __shared__ float pw[QB][PWW];      // probs at (col - wb), wb = lo & ~3

    const int b = blockIdx.z, h = blockIdx.y;
    const int q0 = blockIdx.x * QB;
    const int tid = threadIdx.x;
    const int warp = tid >> 5, lane = tid & 31;

    const int tbase = q0 - HWIN;
    const int glo = tbase < 0 ? 0 : tbase;
    int ghi = q0 + QB - 1 + HWIN; if (ghi > SEQ - 1) ghi = SEQ - 1;
    const int nrows = ghi - glo + 1;
    const int sh0 = glo - tbase;

    if (tid < QB * 16) {
        int qi = tid >> 4, d4 = tid & 15;
        qs4[qi][d4] = ((const float4*)(Qg + (size_t)(b * SEQ + q0 + qi) * DMODEL + h * HDIM))[d4];
    }
    for (int idx = tid; idx < nrows * 16; idx += 512) {
        int r = idx >> 4, d4 = idx & 15;
        tile4[sh0 + r][d4] =
            ((const float4*)(Kg + (size_t)(b * SEQ + glo + r) * DMODEL + h * HDIM))[d4];
    }
    __syncthreads();

    // scores: thread -> (key row, query-octet)
    {
        const int r = tid >> 1;
        const int qh = (tid & 1) * 8;
        if (r >= sh0 && r < sh0 + nrows) {
            float s[8];
#pragma unroll
            for (int qi = 0; qi < 8; qi++) s[qi] = 0.f;
#pragma unroll
            for (int d4 = 0; d4 < 16; d4++) {
                float4 kv = tile4[r][d4];
#pragma unroll
                for (int qi = 0; qi < 8; qi++) {
                    float4 qv = qs4[qh + qi][d4];
                    s[qi] += qv.x * kv.x + qv.y * kv.y + qv.z * kv.z + qv.w * kv.w;
                }
            }
#pragma unroll
            for (int qi = 0; qi < 8; qi++) ps[qh + qi][r] = s[qi];
        }
    }
    __syncthreads();

    // softmax + full-row attn write: warp = query
    {
        const int i = q0 + warp;
        int lo = i - HWIN; if (lo < 0) lo = 0;
        int hi = i + HWIN; if (hi > SEQ - 1) hi = SEQ - 1;
        const int nk = hi - lo + 1;
        const int soff = lo - tbase;
        const int wb = lo & ~3;          // 4-aligned window base
        const int wo = lo - wb;          // 0..3

        float sc[5]; bool valid[5];
#pragma unroll
        for (int c = 0; c < 5; c++) {
            int jj = lane + 32 * c;
            valid[c] = (jj < nk);
            int idx = soff + (valid[c] ? jj : (nk - 1));
            sc[c] = valid[c] ? ps[warp][idx] * 0.125f : -1e30f;
        }
        float mx = -1e30f;
#pragma unroll
        for (int c = 0; c < 5; c++) mx = fmaxf(mx, sc[c]);
#pragma unroll
        for (int o = 16; o; o >>= 1) mx = fmaxf(mx, __shfl_xor_sync(0xffffffffu, mx, o));
        float sum = 0.f;
#pragma unroll
        for (int c = 0; c < 5; c++) {
            sc[c] = valid[c] ? __expf(sc[c] - mx) : 0.f;
            sum += sc[c];
        }
#pragma unroll
        for (int o = 16; o; o >>= 1) sum += __shfl_xor_sync(0xffffffffu, sum, o);
        const float inv = 1.f / sum;

        // zero ENTIRE prob window (PWW = 160 = 5*32), then write band probs
#pragma unroll
        for (int k = 0; k < PWW / 32; k++) pw[warp][lane + 32 * k] = 0.f;
        __syncwarp();
#pragma unroll
        for (int c = 0; c < 5; c++) {
            int jj = lane + 32 * c;
            if (jj < nk) pw[warp][wo + jj] = sc[c] * inv;
        }
        __syncwarp();

        // stream the full 2048-col row: zeros outside window, probs inside
        float4* row4 = (float4*)(attn + ((((size_t)b * NHEAD + h) * SEQ) + i) * SEQ);
        const int wb4 = wb >> 2;                  // window start in float4 units
        const int we4 = (wo + nk + 3) >> 2;       // window f4 count
#pragma unroll
        for (int u = 0; u < 16; u++) {
            int f4i = u * 32 + lane;              // float4 col index 0..511
            int off = f4i - wb4;
            float4 v = make_float4(0.f, 0.f, 0.f, 0.f);
            if (off >= 0 && off < we4)
                v = *(const float4*)&pw[warp][off << 2];
            __stcs(row4 + f4i, v);
        }
    }
    __syncthreads();

    // load V
    for (int idx = tid; idx < nrows * 16; idx += 512) {
        int r = idx >> 4, d4 = idx & 15;
        tile4[sh0 + r][d4] =
            ((const float4*)(Vg + (size_t)(b * SEQ + glo + r) * DMODEL + h * HDIM))[d4];
    }
    __syncthreads();

    // ctx: warp = query; lane -> (d4 = lane&15, key half = lane>>4)
    {
        const int qi = warp;
        const int d4 = lane & 15;
        const int kh = lane >> 4;

        const int iq = q0 + qi;
        int loq = iq - HWIN; if (loq < 0) loq = 0;
        int hiq = iq + HWIN; if (hiq > SEQ - 1) hiq = SEQ - 1;
        const int nkq = hiq - loq + 1;
        const int soq = loq - tbase;
        const int pwo = loq & 3;          // prob window offset for this query

        float4 acc = make_float4(0.f, 0.f, 0.f, 0.f);
        for (int j = kh; j < nkq; j += 2) {
            float p = pw[qi][pwo + j];
            float4 vv = tile4[soq + j][d4];
            acc.x += p * vv.x; acc.y += p * vv.y;
            acc.z += p * vv.z; acc.w += p * vv.w;
        }
        acc.x += __shfl_xor_sync(0xffffffffu, acc.x, 16);
        acc.y += __shfl_xor_sync(0xffffffffu, acc.y, 16);
        acc.z += __shfl_xor_sync(0xffffffffu, acc.z, 16);
        acc.w += __shfl_xor_sync(0xffffffffu, acc.w, 16);

        if (kh == 0)
            ((float4*)(ctx + (size_t)(b * SEQ + iq) * DMODEL + h * HDIM))[d4] = acc;
    }
}

// ---------------- launch ---------------------------------------------------
extern "C" void kernel_launch(void* const* d_in, const int* in_sizes, int n_in,
                              void* d_out, int out_size)
{
    const float* x  = (const float*)d_in[0];
    const float* Wq = (const float*)d_in[1];
    const float* bq = (const float*)d_in[2];
    const float* Wk = (const float*)d_in[3];
    const float* bk = (const float*)d_in[4];
    const float* Wv = (const float*)d_in[5];
    const float* bv = (const float*)d_in[6];
    const float* Wo = (const float*)d_in[7];
    const float* bo = (const float*)d_in[8];

    float* out  = (float*)d_out;
    float* attn = out + (size_t)MROWS * DMODEL;

    float *pq, *pk, *pv, *pc;
    cudaGetSymbolAddress((void**)&pq, g_q);
    cudaGetSymbolAddress((void**)&pk, g_k);
    cudaGetSymbolAddress((void**)&pv, g_v);
    cudaGetSymbolAddress((void**)&pc, g_ctx);
    __nv_bfloat16 *xh, *xl, *ch, *cl, *wh, *wl;
    cudaGetSymbolAddress((void**)&xh, g_xh);
    cudaGetSymbolAddress((void**)&xl, g_xl);
    cudaGetSymbolAddress((void**)&ch, g_ch);
    cudaGetSymbolAddress((void**)&cl, g_cl);
    cudaGetSymbolAddress((void**)&wh, g_wh);
    cudaGetSymbolAddress((void**)&wl, g_wl);

    cudaFuncSetAttribute(gemm_tc, cudaFuncAttributeMaxDynamicSharedMemorySize, GEMM_SMEM);

    const size_t WSZ = (size_t)DMODEL * DMODEL;
    split_bf16<<<512, 256>>>(x, xh, xl, MROWS * DMODEL / 4);
    split_bf16x4<<<1024, 256>>>(Wq, Wk, Wv, Wo, wh, wl, (int)(WSZ / 4));

    dim3 gqkv(DMODEL / 128, MROWS / 128, 3);
    gemm_tc<<<gqkv, 512, GEMM_SMEM>>>(xh, xl, wh, wl, bq, bk, bv, pq, pk, pv);

    dim3 gattn(SEQ / QB, NHEAD, BATCH);
    local_attn_kernel<<<gattn, 512>>>(pq, pk, pv, attn, pc);

    split_bf16<<<512, 256>>>(pc, ch, cl, MROWS * DMODEL / 4);
    dim3 gout(DMODEL / 128, MROWS / 128, 1);
    gemm_tc<<<gout, 512, GEMM_SMEM>>>(ch, cl, wh + 3 * WSZ, wl + 3 * WSZ,
                                      bo, bo, bo, out, out, out);
}

// round 15
// speedup vs baseline: 1.1092x; 1.1092x over previous
#include <cuda_runtime.h>
#include <cuda_bf16.h>
#include <cstdint>

#define BATCH 2
#define SEQ   2048
#define DMODEL 1024
#define NHEAD 16
#define HDIM  64
#define HWIN  64
#define MROWS (BATCH*SEQ)

// ---------------- scratch ----------------
__device__ float g_q[(size_t)MROWS * DMODEL];
__device__ float g_k[(size_t)MROWS * DMODEL];
__device__ float g_v[(size_t)MROWS * DMODEL];
__device__ float g_ctx[(size_t)MROWS * DMODEL];
__device__ __nv_bfloat16 g_xh[(size_t)MROWS * DMODEL];
__device__ __nv_bfloat16 g_xl[(size_t)MROWS * DMODEL];
__device__ __nv_bfloat16 g_ch[(size_t)MROWS * DMODEL];
__device__ __nv_bfloat16 g_cl[(size_t)MROWS * DMODEL];
__device__ __nv_bfloat16 g_wh[4][(size_t)DMODEL * DMODEL];
__device__ __nv_bfloat16 g_wl[4][(size_t)DMODEL * DMODEL];

// ---------------- helpers ----------------
__device__ __forceinline__ uint32_t smem_u32(const void* p) {
    uint32_t a;
    asm("{ .reg .u64 t; cvta.to.shared.u64 t, %1; cvt.u32.u64 %0, t; }" : "=r"(a) : "l"(p));
    return a;
}
__device__ __forceinline__ void cp16(uint32_t s, const void* g) {
    asm volatile("cp.async.cg.shared.global [%0], [%1], 16;" :: "r"(s), "l"(g));
}
#define CP_COMMIT() asm volatile("cp.async.commit_group;" ::: "memory")
#define CP_WAIT0()  asm volatile("cp.async.wait_group 0;" ::: "memory")

#define LDSM_X4(r0,r1,r2,r3,addr) \
    asm volatile("ldmatrix.sync.aligned.m8n8.x4.shared.b16 {%0,%1,%2,%3}, [%4];" \
                 : "=r"(r0), "=r"(r1), "=r"(r2), "=r"(r3) : "r"(addr))

#define MMA16816(d, a0,a1,a2,a3, b0,b1) \
    asm volatile("mma.sync.aligned.m16n8k16.row.col.f32.bf16.bf16.f32 " \
                 "{%0,%1,%2,%3}, {%4,%5,%6,%7}, {%8,%9}, {%0,%1,%2,%3};" \
                 : "+f"((d)[0]), "+f"((d)[1]), "+f"((d)[2]), "+f"((d)[3]) \
                 : "r"(a0), "r"(a1), "r"(a2), "r"(a3), "r"(b0), "r"(b1))

// ---------------- split fp32 -> bf16 hi + bf16 residual --------------------
__device__ __forceinline__ void split1(float4 v, uint2& hp, uint2& lp) {
    __nv_bfloat16 hx = __float2bfloat16(v.x), hy = __float2bfloat16(v.y);
    __nv_bfloat16 hz = __float2bfloat16(v.z), hw = __float2bfloat16(v.w);
    float lx = v.x - __bfloat162float(hx), ly = v.y - __bfloat162float(hy);
    float lz = v.z - __bfloat162float(hz), lw = v.w - __bfloat162float(hw);
    hp.x = ((uint32_t)__bfloat16_as_ushort(hy) << 16) | __bfloat16_as_ushort(hx);
    hp.y = ((uint32_t)__bfloat16_as_ushort(hw) << 16) | __bfloat16_as_ushort(hz);
    lp.x = ((uint32_t)__bfloat16_as_ushort(__float2bfloat16(ly)) << 16) |
           __bfloat16_as_ushort(__float2bfloat16(lx));
    lp.y = ((uint32_t)__bfloat16_as_ushort(__float2bfloat16(lw)) << 16) |
           __bfloat16_as_ushort(__float2bfloat16(lz));
}

__global__ __launch_bounds__(256) void split_bf16(
    const float* __restrict__ src, __nv_bfloat16* __restrict__ hi,
    __nv_bfloat16* __restrict__ lo, int n4)
{
    int idx = blockIdx.x * 256 + threadIdx.x;
    int stride = gridDim.x * 256;
    for (; idx < n4; idx += stride) {
        uint2 hp, lp;
        split1(((const float4*)src)[idx], hp, lp);
        ((uint2*)hi)[idx] = hp;
        ((uint2*)lo)[idx] = lp;
    }
}

__global__ __launch_bounds__(256) void split_bf16x4(
    const float* __restrict__ s0, const float* __restrict__ s1,
    const float* __restrict__ s2, const float* __restrict__ s3,
    __nv_bfloat16* __restrict__ hi, __nv_bfloat16* __restrict__ lo, int per4)
{
    int idx = blockIdx.x * 256 + threadIdx.x;
    int stride = gridDim.x * 256;
    int n4 = 4 * per4;
    for (; idx < n4; idx += stride) {
        int m = idx / per4, loc = idx - m * per4;
        const float* s = (m == 0) ? s0 : (m == 1) ? s1 : (m == 2) ? s2 : s3;
        uint2 hp, lp;
        split1(((const float4*)s)[loc], hp, lp);
        ((uint2*)hi)[idx] = hp;
        ((uint2*)lo)[idx] = lp;
    }
}

// -------- tensor GEMM: fat chunks (Ah/Al/Bh/Bl co-resident), frag reuse ----
#define ROWB   80
#define TILEB  (128 * ROWB)
#define STAGE  (4 * TILEB)
#define NSTG   2
#define GEMM_SMEM (NSTG * STAGE)
#define NCHUNK 32

__global__ __launch_bounds__(512, 2) void gemm_tc(
    const __nv_bfloat16* __restrict__ Ah, const __nv_bfloat16* __restrict__ Al,
    const __nv_bfloat16* __restrict__ Whbase, const __nv_bfloat16* __restrict__ Wlbase,
    const float* __restrict__ bias0, const float* __restrict__ bias1,
    const float* __restrict__ bias2,
    float* __restrict__ C0, float* __restrict__ C1, float* __restrict__ C2)
{
    extern __shared__ char smem[];
    const uint32_t tiles = smem_u32(smem);

    const int z = blockIdx.z;
    const size_t WSZ = (size_t)DMODEL * DMODEL;
    const __nv_bfloat16* Bh = Whbase + (size_t)z * WSZ;
    const __nv_bfloat16* Bl = Wlbase + (size_t)z * WSZ;
    const float* bias = (z == 0) ? bias0 : (z == 1) ? bias1 : bias2;
    float* C = (z == 0) ? C0 : (z == 1) ? C1 : C2;

    const int tid = threadIdx.x;
    const int wid = tid >> 5, lane = tid & 31;
    const int wm = wid >> 2;
    const int wn = wid & 3;
    const int bm = blockIdx.y * 128;
    const int bn = blockIdx.x * 128;

    const int lr = tid >> 2;
    const int q16 = (tid & 3) * 16;

    float acc[2][4][4];
#pragma unroll
    for (int i = 0; i < 2; i++)
#pragma unroll
        for (int j = 0; j < 4; j++)
#pragma unroll
            for (int k = 0; k < 4; k++) acc[i][j][k] = 0.f;

    auto issue_load = [&](int c) {
        const int kk = c * 32;
        const size_t arow = (size_t)(bm + lr) * DMODEL + kk + q16 / 2;
        const size_t brow = (size_t)(bn + lr) * DMODEL + kk + q16 / 2;
        const uint32_t st = tiles + (c & 1) * STAGE;
        const uint32_t so = lr * ROWB + q16;
        cp16(st + so, Ah + arow);
        cp16(st + TILEB + so, Al + arow);
        cp16(st + 2 * TILEB + so, Bh + brow);
        cp16(st + 3 * TILEB + so, Bl + brow);
    };

    issue_load(0); CP_COMMIT();

    const uint32_t a_lrow = (uint32_t)(lane & 15) * ROWB + (uint32_t)(lane >> 4) * 16;
    const uint32_t b_lrow = (uint32_t)((lane >> 4) * 8 + (lane & 7)) * ROWB +
                            (uint32_t)((lane >> 3) & 1) * 16;

    for (int c = 0; c < NCHUNK; c++) {
        CP_WAIT0();
        __syncthreads();
        if (c + 1 < NCHUNK) issue_load(c + 1);
        CP_COMMIT();

        const uint32_t st = tiles + (c & 1) * STAGE;
        const uint32_t ahb = st + (uint32_t)(wm * 32) * ROWB + a_lrow;
        const uint32_t bhb = st + 2 * TILEB + (uint32_t)(wn * 32) * ROWB + b_lrow;

#pragma unroll
        for (int ks = 0; ks < 2; ks++) {
            const uint32_t koff = ks * 32;
            uint32_t ah[2][4], bh_[2][4], tf[2][4];
#pragma unroll
            for (int mt = 0; mt < 2; mt++)
                LDSM_X4(ah[mt][0], ah[mt][1], ah[mt][2], ah[mt][3],
                        ahb + (uint32_t)(mt * 16) * ROWB + koff);
#pragma unroll
            for (int np = 0; np < 2; np++)
                LDSM_X4(bh_[np][0], bh_[np][1], bh_[np][2], bh_[np][3],
                        bhb + (uint32_t)(np * 16) * ROWB + koff);
#pragma unroll
            for (int mt = 0; mt < 2; mt++)
#pragma unroll
                for (int nt = 0; nt < 4; nt++)
                    MMA16816(acc[mt][nt], ah[mt][0], ah[mt][1], ah[mt][2], ah[mt][3],
                             bh_[nt >> 1][(nt & 1) * 2], bh_[nt >> 1][(nt & 1) * 2 + 1]);
#pragma unroll
            for (int mt = 0; mt < 2; mt++)
                LDSM_X4(tf[mt][0], tf[mt][1], tf[mt][2], tf[mt][3],
                        ahb + TILEB + (uint32_t)(mt * 16) * ROWB + koff);
#pragma unroll
            for (int mt = 0; mt < 2; mt++)
#pragma unroll
                for (int nt = 0; nt < 4; nt++)
                    MMA16816(acc[mt][nt], tf[mt][0], tf[mt][1], tf[mt][2], tf[mt][3],
                             bh_[nt >> 1][(nt & 1) * 2], bh_[nt >> 1][(nt & 1) * 2 + 1]);
#pragma unroll
            for (int np = 0; np < 2; np++)
                LDSM_X4(tf[np][0], tf[np][1], tf[np][2], tf[np][3],
                        bhb + TILEB + (uint32_t)(np * 16) * ROWB + koff);
#pragma unroll
            for (int mt = 0; mt < 2; mt++)
#pragma unroll
                for (int nt = 0; nt < 4; nt++)
                    MMA16816(acc[mt][nt], ah[mt][0], ah[mt][1], ah[mt][2], ah[mt][3],
                             tf[nt >> 1][(nt & 1) * 2], tf[nt >> 1][(nt & 1) * 2 + 1]);
        }
    }

#pragma unroll
    for (int mt = 0; mt < 2; mt++) {
#pragma unroll
        for (int nt = 0; nt < 4; nt++) {
            const int r0 = bm + wm * 32 + mt * 16 + (lane >> 2);
            const int cc = bn + wn * 32 + nt * 8 + (lane & 3) * 2;
            const float b0 = bias[cc], b1 = bias[cc + 1];
            float2 v0, v1;
            v0.x = acc[mt][nt][0] + b0; v0.y = acc[mt][nt][1] + b1;
            v1.x = acc[mt][nt][2] + b0; v1.y = acc[mt][nt][3] + b1;
            *(float2*)&C[(size_t)r0 * DMODEL + cc] = v0;
            *(float2*)&C[(size_t)(r0 + 8) * DMODEL + cc] = v1;
        }
    }
}

// ---------------- banded attention: full-row single-pass writes ------------
#define QB 16
#define KSPAN 144
#define TPAD 17
#define PWW 160     // 5 x 32: warp zero-loop covers entire window

__global__ __launch_bounds__(512, 2) void local_attn_kernel(
    const float* __restrict__ Qg, const float* __restrict__ Kg,
    const float* __restrict__ Vg, float* __restrict__ attn,
    float* __restrict__ ctx)
{
    __shared__ float4 tile4[KSPAN][TPAD];
    __shared__ float4 qs4[QB][TPAD];
    __shared__ float ps[QB][KSPAN];
    __shared__ float pw[QB][PWW];

    const int b = blockIdx.z, h = blockIdx.y;
    const int q0 = blockIdx.x * QB;
    const int tid = threadIdx.x;
    const int warp = tid >> 5, lane = tid & 31;

    const int tbase = q0 - HWIN;
    const int glo = tbase < 0 ? 0 : tbase;
    int ghi = q0 + QB - 1 + HWIN; if (ghi > SEQ - 1) ghi = SEQ - 1;
    const int nrows = ghi - glo + 1;
    const int sh0 = glo - tbase;

    if (tid < QB * 16) {
        int qi = tid >> 4, d4 = tid & 15;
        qs4[qi][d4] = ((const float4*)(Qg + (size_t)(b * SEQ + q0 + qi) * DMODEL + h * HDIM))[d4];
    }
    for (int idx = tid; idx < nrows * 16; idx += 512) {
        int r = idx >> 4, d4 = idx & 15;
        tile4[sh0 + r][d4] =
            ((const float4*)(Kg + (size_t)(b * SEQ + glo + r) * DMODEL + h * HDIM))[d4];
    }
    __syncthreads();

    // scores: thread -> (key row, query-octet)
    {
        const int r = tid >> 1;
        const int qh = (tid & 1) * 8;
        if (r >= sh0 && r < sh0 + nrows) {
            float s[8];
#pragma unroll
            for (int qi = 0; qi < 8; qi++) s[qi] = 0.f;
#pragma unroll
            for (int d4 = 0; d4 < 16; d4++) {
                float4 kv = tile4[r][d4];
#pragma unroll
                for (int qi = 0; qi < 8; qi++) {
                    float4 qv = qs4[qh + qi][d4];
                    s[qi] += qv.x * kv.x + qv.y * kv.y + qv.z * kv.z + qv.w * kv.w;
                }
            }
#pragma unroll
            for (int qi = 0; qi < 8; qi++) ps[qh + qi][r] = s[qi];
        }
    }
    __syncthreads();

    // softmax + full-row attn write: warp = query
    {
        const int i = q0 + warp;
        int lo = i - HWIN; if (lo < 0) lo = 0;
        int hi = i + HWIN; if (hi > SEQ - 1) hi = SEQ - 1;
        const int nk = hi - lo + 1;
        const int soff = lo - tbase;
        const int wb = lo & ~3;
        const int wo = lo - wb;

        float sc[5]; bool valid[5];
#pragma unroll
        for (int c = 0; c < 5; c++) {
            int jj = lane + 32 * c;
            valid[c] = (jj < nk);
            int idx = soff + (valid[c] ? jj : (nk - 1));
            sc[c] = valid[c] ? ps[warp][idx] * 0.125f : -1e30f;
        }
        float mx = -1e30f;
#pragma unroll
        for (int c = 0; c < 5; c++) mx = fmaxf(mx, sc[c]);
#pragma unroll
        for (int o = 16; o; o >>= 1) mx = fmaxf(mx, __shfl_xor_sync(0xffffffffu, mx, o));
        float sum = 0.f;
#pragma unroll
        for (int c = 0; c < 5; c++) {
            sc[c] = valid[c] ? __expf(sc[c] - mx) : 0.f;
            sum += sc[c];
        }
#pragma unroll
        for (int o = 16; o; o >>= 1) sum += __shfl_xor_sync(0xffffffffu, sum, o);
        const float inv = 1.f / sum;

#pragma unroll
        for (int k = 0; k < PWW / 32; k++) pw[warp][lane + 32 * k] = 0.f;
        __syncwarp();
#pragma unroll
        for (int c = 0; c < 5; c++) {
            int jj = lane + 32 * c;
            if (jj < nk) pw[warp][wo + jj] = sc[c] * inv;
        }
        __syncwarp();

        // stream full 2048-col row (moderate unroll to keep regs in check)
        float4* row4 = (float4*)(attn + ((((size_t)b * NHEAD + h) * SEQ) + i) * SEQ);
        const int wb4 = wb >> 2;
        const int we4 = (wo + nk + 3) >> 2;
#pragma unroll 4
        for (int u = 0; u < 16; u++) {
            int f4i = u * 32 + lane;
            int off = f4i - wb4;
            float4 v = make_float4(0.f, 0.f, 0.f, 0.f);
            if (off >= 0 && off < we4)
                v = *(const float4*)&pw[warp][off << 2];
            __stcs(row4 + f4i, v);
        }
    }
    __syncthreads();

    // load V
    for (int idx = tid; idx < nrows * 16; idx += 512) {
        int r = idx >> 4, d4 = idx & 15;
        tile4[sh0 + r][d4] =
            ((const float4*)(Vg + (size_t)(b * SEQ + glo + r) * DMODEL + h * HDIM))[d4];
    }
    __syncthreads();

    // ctx
    {
        const int qi = warp;
        const int d4 = lane & 15;
        const int kh = lane >> 4;

        const int iq = q0 + qi;
        int loq = iq - HWIN; if (loq < 0) loq = 0;
        int hiq = iq + HWIN; if (hiq > SEQ - 1) hiq = SEQ - 1;
        const int nkq = hiq - loq + 1;
        const int soq = loq - tbase;
        const int pwo = loq & 3;

        float4 acc = make_float4(0.f, 0.f, 0.f, 0.f);
        for (int j = kh; j < nkq; j += 2) {
            float p = pw[qi][pwo + j];
            float4 vv = tile4[soq + j][d4];
            acc.x += p * vv.x; acc.y += p * vv.y;
            acc.z += p * vv.z; acc.w += p * vv.w;
        }
        acc.x += __shfl_xor_sync(0xffffffffu, acc.x, 16);
        acc.y += __shfl_xor_sync(0xffffffffu, acc.y, 16);
        acc.z += __shfl_xor_sync(0xffffffffu, acc.z, 16);
        acc.w += __shfl_xor_sync(0xffffffffu, acc.w, 16);

        if (kh == 0)
            ((float4*)(ctx + (size_t)(b * SEQ + iq) * DMODEL + h * HDIM))[d4] = acc;
    }
}

// ---------------- launch ---------------------------------------------------
extern "C" void kernel_launch(void* const* d_in, const int* in_sizes, int n_in,
                              void* d_out, int out_size)
{
    const float* x  = (const float*)d_in[0];
    const float* Wq = (const float*)d_in[1];
    const float* bq = (const float*)d_in[2];
    const float* Wk = (const float*)d_in[3];
    const float* bk = (const float*)d_in[4];
    const float* Wv = (const float*)d_in[5];
    const float* bv = (const float*)d_in[6];
    const float* Wo = (const float*)d_in[7];
    const float* bo = (const float*)d_in[8];

    float* out  = (float*)d_out;
    float* attn = out + (size_t)MROWS * DMODEL;

    float *pq, *pk, *pv, *pc;
    cudaGetSymbolAddress((void**)&pq, g_q);
    cudaGetSymbolAddress((void**)&pk, g_k);
    cudaGetSymbolAddress((void**)&pv, g_v);
    cudaGetSymbolAddress((void**)&pc, g_ctx);
    __nv_bfloat16 *xh, *xl, *ch, *cl, *wh, *wl;
    cudaGetSymbolAddress((void**)&xh, g_xh);
    cudaGetSymbolAddress((void**)&xl, g_xl);
    cudaGetSymbolAddress((void**)&ch, g_ch);
    cudaGetSymbolAddress((void**)&cl, g_cl);
    cudaGetSymbolAddress((void**)&wh, g_wh);
    cudaGetSymbolAddress((void**)&wl, g_wl);

    cudaFuncSetAttribute(gemm_tc, cudaFuncAttributeMaxDynamicSharedMemorySize, GEMM_SMEM);

    const size_t WSZ = (size_t)DMODEL * DMODEL;
    split_bf16<<<512, 256>>>(x, xh, xl, MROWS * DMODEL / 4);
    split_bf16x4<<<1024, 256>>>(Wq, Wk, Wv, Wo, wh, wl, (int)(WSZ / 4));

    dim3 gqkv(DMODEL / 128, MROWS / 128, 3);
    gemm_tc<<<gqkv, 512, GEMM_SMEM>>>(xh, xl, wh, wl, bq, bk, bv, pq, pk, pv);

    dim3 gattn(SEQ / QB, NHEAD, BATCH);
    local_attn_kernel<<<gattn, 512>>>(pq, pk, pv, attn, pc);

    split_bf16<<<512, 256>>>(pc, ch, cl, MROWS * DMODEL / 4);
    dim3 gout(DMODEL / 128, MROWS / 128, 1);
    gemm_tc<<<gout, 512, GEMM_SMEM>>>(ch, cl, wh + 3 * WSZ, wl + 3 * WSZ,
                                      bo, bo, bo, out, out, out);
}